// round 1
// baseline (speedup 1.0000x reference)
#include <cuda_runtime.h>
#include <math.h>

#define B 4
#define S 800
#define C 768
#define NH 12
#define DH 64
#define HID 3072
#define DEPTH 12
#define ROWS (B*S)   // 3200

// ---------------- scratch (static device globals; no runtime alloc) ----------
__device__ float g_h  [ROWS * C];     // residual stream
__device__ float g_y  [ROWS * C];     // LN output
__device__ float g_qkv[ROWS * 3 * C]; // qkv projection
__device__ float g_kT [B * NH * DH * S]; // K transposed: [b,h,d,s]
__device__ float g_o  [ROWS * C];     // attention output
__device__ float g_h1 [ROWS * HID];   // MLP hidden

// ---------------- patch embed ------------------------------------------------
// one block per (b, s): im2col patch into smem, each thread computes 3 channels
__global__ __launch_bounds__(256) void embed_kernel(
    const float* __restrict__ x, const float* __restrict__ w,
    const float* __restrict__ bias, float* __restrict__ out)
{
    int s = blockIdx.x, b = blockIdx.y, tid = threadIdx.x;
    __shared__ float patch[768];
    int sp    = (s < 400) ? s : s - 400;
    int choff = (s < 400) ? 0 : 3;
    int gh = sp / 20, gw = sp % 20;
    for (int j = tid; j < 768; j += 256) {
        int ci = j >> 8, ph = (j >> 4) & 15, pw = j & 15;
        patch[j] = x[(((size_t)b * 6 + choff + ci) * 320 + gh * 16 + ph) * 320 + gw * 16 + pw];
    }
    __syncthreads();
#pragma unroll
    for (int u = 0; u < 3; u++) {
        int c = tid + u * 256;
        const float4* wr = (const float4*)(w + (size_t)c * 768);
        const float4* pp = (const float4*)patch;
        float acc = bias[c];
#pragma unroll 8
        for (int j4 = 0; j4 < 192; j4++) {
            float4 wv = wr[j4], pv = pp[j4];
            acc += wv.x * pv.x + wv.y * pv.y + wv.z * pv.z + wv.w * pv.w;
        }
        out[((size_t)(b * 800 + s)) * 768 + c] = acc;
    }
}

// ---------------- layernorm --------------------------------------------------
__global__ __launch_bounds__(256) void ln_kernel(
    const float* __restrict__ in, float* __restrict__ out,
    const float* __restrict__ g, const float* __restrict__ bta)
{
    int row = blockIdx.x, tid = threadIdx.x;
    const float* x = in + (size_t)row * C;
    __shared__ float red[256];
    float s = 0.f;
    for (int i = tid; i < C; i += 256) s += x[i];
    red[tid] = s; __syncthreads();
    for (int st = 128; st > 0; st >>= 1) { if (tid < st) red[tid] += red[tid + st]; __syncthreads(); }
    float mean = red[0] / (float)C;
    __syncthreads();
    float v = 0.f;
    for (int i = tid; i < C; i += 256) { float d = x[i] - mean; v += d * d; }
    red[tid] = v; __syncthreads();
    for (int st = 128; st > 0; st >>= 1) { if (tid < st) red[tid] += red[tid + st]; __syncthreads(); }
    float inv = rsqrtf(red[0] / (float)C + 1e-6f);
    float* o = out + (size_t)row * C;
    for (int i = tid; i < C; i += 256) o[i] = (x[i] - mean) * inv * g[i] + bta[i];
}

// ---------------- tiled SGEMM: C = A[MxK] * W[KxN] + bias (+res) (+gelu) -----
__global__ __launch_bounds__(256) void gemm_kernel(
    const float* __restrict__ A, const float* __restrict__ W,
    const float* __restrict__ bias, const float* __restrict__ res,
    float* __restrict__ Cout, int M, int N, int K, int act)
{
    __shared__ float As[16][64];
    __shared__ float Bs[16][64];
    int tid = threadIdx.x;
    int tx = tid & 15, ty = tid >> 4;
    int m0 = blockIdx.y * 64, n0 = blockIdx.x * 64;
    float acc[4][4] = {};

    int arow  = tid >> 2;         // 0..63
    int acol4 = (tid & 3) * 4;    // 0,4,8,12
    int brow  = tid >> 4;         // 0..15
    int bcol4 = (tid & 15) * 4;
    const float* Arow = A + (size_t)(m0 + arow) * K;

    for (int k0 = 0; k0 < K; k0 += 16) {
        float4 a = *(const float4*)(Arow + k0 + acol4);
        As[acol4 + 0][arow] = a.x; As[acol4 + 1][arow] = a.y;
        As[acol4 + 2][arow] = a.z; As[acol4 + 3][arow] = a.w;
        *(float4*)&Bs[brow][bcol4] =
            *(const float4*)(W + (size_t)(k0 + brow) * N + n0 + bcol4);
        __syncthreads();
#pragma unroll
        for (int k = 0; k < 16; k++) {
            float4 av = *(const float4*)&As[k][ty * 4];
            float4 bw = *(const float4*)&Bs[k][tx * 4];
            float aa[4] = {av.x, av.y, av.z, av.w};
            float bb[4] = {bw.x, bw.y, bw.z, bw.w};
#pragma unroll
            for (int i = 0; i < 4; i++)
#pragma unroll
                for (int j = 0; j < 4; j++) acc[i][j] += aa[i] * bb[j];
        }
        __syncthreads();
    }
    float4 b4 = *(const float4*)(bias + n0 + tx * 4);
    float bb[4] = {b4.x, b4.y, b4.z, b4.w};
#pragma unroll
    for (int i = 0; i < 4; i++) {
        int row = m0 + ty * 4 + i;
        float vals[4];
#pragma unroll
        for (int j = 0; j < 4; j++) {
            float v = acc[i][j] + bb[j];
            if (res) v += res[(size_t)row * N + n0 + tx * 4 + j];
            if (act == 1) v = 0.5f * v * (1.f + erff(v * 0.70710678118654752f));
            vals[j] = v;
        }
        *(float4*)(Cout + (size_t)row * N + n0 + tx * 4) =
            make_float4(vals[0], vals[1], vals[2], vals[3]);
    }
}

// ---------------- RoPE: rotate q (in place) and k (into transposed buf) ------
// angle(d) = s * 10000^(-(d mod 32)/32); out[2i] = t[2i]c(2i) - t[2i+1]s(2i),
// out[2i+1] = t[2i+1]c(2i+1) + t[2i]s(2i+1)
__global__ __launch_bounds__(256) void rope_kernel(float* __restrict__ qkv,
                                                   float* __restrict__ kT)
{
    int idx = blockIdx.x * blockDim.x + threadIdx.x;
    const int TOT = B * S * NH * (DH / 2);
    if (idx >= TOT) return;
    int d2 = idx & 31;
    int h  = (idx >> 5) % NH;
    int bs = idx / (32 * NH);
    int s  = bs % S;
    int b  = bs / S;
    float* qp = qkv + (size_t)bs * (3 * C) + h * DH;
    float* kp = qp + C;
    int d0 = 2 * d2, d1 = 2 * d2 + 1;
    float a0 = (float)s * powf(10000.f, -(float)(d0 & 31) / 32.f);
    float a1 = (float)s * powf(10000.f, -(float)(d1 & 31) / 32.f);
    float c0 = cosf(a0), s0 = sinf(a0);
    float c1 = cosf(a1), s1 = sinf(a1);
    float q0 = qp[d0], q1 = qp[d1];
    qp[d0] = q0 * c0 - q1 * s0;
    qp[d1] = q1 * c1 + q0 * s1;
    float k0 = kp[d0], k1 = kp[d1];
    float kn0 = k0 * c0 - k1 * s0;
    float kn1 = k1 * c1 + k0 * s1;
    int bh = b * NH + h;
    kT[((size_t)bh * DH + d0) * S + s] = kn0;
    kT[((size_t)bh * DH + d1) * S + s] = kn1;
}

// ---------------- attention: one block per (bh, s) ---------------------------
__global__ __launch_bounds__(256) void attn_kernel(const float* __restrict__ qkv,
                                                   const float* __restrict__ kT,
                                                   float* __restrict__ o)
{
    int s = blockIdx.x, bh = blockIdx.y;
    int b = bh / NH, h = bh % NH;
    int tid = threadIdx.x;
    __shared__ float sc[S];
    __shared__ float red[256];
    __shared__ float qv[DH];
    const float* qrow = qkv + ((size_t)(b * S + s)) * (3 * C) + h * DH;
    if (tid < DH) qv[tid] = qrow[tid];
    __syncthreads();

    const float* kbase = kT + (size_t)bh * DH * S;
    float lmax = -1e30f;
    for (int t = tid; t < S; t += 256) {
        float acc = 0.f;
#pragma unroll
        for (int d = 0; d < DH; d++) acc += qv[d] * kbase[(size_t)d * S + t];
        acc *= 0.125f;   // DH^-0.5
        sc[t] = acc;
        lmax = fmaxf(lmax, acc);
    }
    red[tid] = lmax; __syncthreads();
    for (int st = 128; st > 0; st >>= 1) { if (tid < st) red[tid] = fmaxf(red[tid], red[tid + st]); __syncthreads(); }
    float m = red[0]; __syncthreads();
    float lsum = 0.f;
    for (int t = tid; t < S; t += 256) { float p = expf(sc[t] - m); sc[t] = p; lsum += p; }
    red[tid] = lsum; __syncthreads();
    for (int st = 128; st > 0; st >>= 1) { if (tid < st) red[tid] += red[tid + st]; __syncthreads(); }
    float inv = 1.f / red[0];
    __syncthreads();

    // o[d] = sum_t p[t] v[t,d] * inv ; 4 chunks of 200 t's, lane d coalesced
    int d = tid & 63, c = tid >> 6;
    float acc = 0.f;
    const float* vbase = qkv + 2 * C + h * DH + d;
    for (int t = c * 200; t < (c + 1) * 200; t++)
        acc += sc[t] * vbase[((size_t)(b * S + t)) * (3 * C)];
    red[tid] = acc; __syncthreads();
    if (tid < 64) {
        float r = red[tid] + red[tid + 64] + red[tid + 128] + red[tid + 192];
        o[((size_t)(b * S + s)) * C + h * DH + tid] = r * inv;
    }
}

// ---------------- host orchestration ----------------------------------------
extern "C" void kernel_launch(void* const* d_in, const int* in_sizes, int n_in,
                              void* d_out, int out_size)
{
    const float* x      = (const float*)d_in[0];
    const float* conv_w = (const float*)d_in[1];
    const float* conv_b = (const float*)d_in[2];
    const float* ln1_g  = (const float*)d_in[3];
    const float* ln1_b  = (const float*)d_in[4];
    const float* qkv_w  = (const float*)d_in[5];
    const float* qkv_b  = (const float*)d_in[6];
    const float* proj_w = (const float*)d_in[7];
    const float* proj_b = (const float*)d_in[8];
    const float* ln2_g  = (const float*)d_in[9];
    const float* ln2_b  = (const float*)d_in[10];
    const float* fc1_w  = (const float*)d_in[11];
    const float* fc1_b  = (const float*)d_in[12];
    const float* fc2_w  = (const float*)d_in[13];
    const float* fc2_b  = (const float*)d_in[14];
    const float* lnf_g  = (const float*)d_in[15];
    const float* lnf_b  = (const float*)d_in[16];
    float* out = (float*)d_out;

    float *h_p, *y_p, *qkv_p, *kT_p, *o_p, *h1_p;
    cudaGetSymbolAddress((void**)&h_p,   g_h);
    cudaGetSymbolAddress((void**)&y_p,   g_y);
    cudaGetSymbolAddress((void**)&qkv_p, g_qkv);
    cudaGetSymbolAddress((void**)&kT_p,  g_kT);
    cudaGetSymbolAddress((void**)&o_p,   g_o);
    cudaGetSymbolAddress((void**)&h1_p,  g_h1);

    // patch embed -> g_h
    embed_kernel<<<dim3(S, B), 256>>>(x, conv_w, conv_b, h_p);

    const int ropeN = B * S * NH * (DH / 2);
    for (int l = 0; l < DEPTH; l++) {
        // ln1
        ln_kernel<<<ROWS, 256>>>(h_p, y_p, ln1_g + l * C, ln1_b + l * C);
        // qkv = y @ W + b
        gemm_kernel<<<dim3((3 * C) / 64, ROWS / 64), 256>>>(
            y_p, qkv_w + (size_t)l * C * 3 * C, qkv_b + (size_t)l * 3 * C,
            nullptr, qkv_p, ROWS, 3 * C, C, 0);
        // rope (q in place, k -> kT)
        rope_kernel<<<(ropeN + 255) / 256, 256>>>(qkv_p, kT_p);
        // attention -> g_o
        attn_kernel<<<dim3(S, B * NH), 256>>>(qkv_p, kT_p, o_p);
        // h += o @ proj + b
        gemm_kernel<<<dim3(C / 64, ROWS / 64), 256>>>(
            o_p, proj_w + (size_t)l * C * C, proj_b + (size_t)l * C,
            h_p, h_p, ROWS, C, C, 0);
        // ln2
        ln_kernel<<<ROWS, 256>>>(h_p, y_p, ln2_g + l * C, ln2_b + l * C);
        // h1 = gelu(y @ fc1 + b)
        gemm_kernel<<<dim3(HID / 64, ROWS / 64), 256>>>(
            y_p, fc1_w + (size_t)l * C * HID, fc1_b + (size_t)l * HID,
            nullptr, h1_p, ROWS, HID, C, 1);
        // h += h1 @ fc2 + b
        gemm_kernel<<<dim3(C / 64, ROWS / 64), 256>>>(
            h1_p, fc2_w + (size_t)l * HID * C, fc2_b + (size_t)l * C,
            h_p, h_p, ROWS, C, HID, 0);
    }
    // final LN -> out
    ln_kernel<<<ROWS, 256>>>(h_p, out, lnf_g, lnf_b);
}

// round 3
// speedup vs baseline: 1.6457x; 1.6457x over previous
#include <cuda_runtime.h>
#include <cuda_bf16.h>
#include <math.h>
#include <stdint.h>

#define B 4
#define S 800
#define C 768
#define NH 12
#define DH 64
#define HID 3072
#define DEPTH 12
#define ROWS (B*S)   // 3200

// ---------------- scratch (static device globals; no runtime alloc) ----------
__device__ float g_h  [ROWS * C];
__device__ float g_qkv[ROWS * 3 * C];
__device__ float g_kT [B * NH * DH * S];

// bf16 split weights, transposed to [N,K] per layer
__device__ __nv_bfloat16 g_wq_h[DEPTH * 2304 * 768];
__device__ __nv_bfloat16 g_wq_l[DEPTH * 2304 * 768];
__device__ __nv_bfloat16 g_wp_h[DEPTH * 768 * 768];
__device__ __nv_bfloat16 g_wp_l[DEPTH * 768 * 768];
__device__ __nv_bfloat16 g_w1_h[DEPTH * 3072 * 768];
__device__ __nv_bfloat16 g_w1_l[DEPTH * 3072 * 768];
__device__ __nv_bfloat16 g_w2_h[DEPTH * 768 * 3072];
__device__ __nv_bfloat16 g_w2_l[DEPTH * 768 * 3072];
// bf16 split activations
__device__ __nv_bfloat16 g_ah [ROWS * C];
__device__ __nv_bfloat16 g_al [ROWS * C];
__device__ __nv_bfloat16 g_h1h[ROWS * HID];
__device__ __nv_bfloat16 g_h1l[ROWS * HID];

// ---------------- helpers ------------------------------------------------
static __device__ __forceinline__ uint32_t s2u(const void* p) {
    uint32_t a;
    asm("{ .reg .u64 t; cvta.to.shared.u64 t, %1; cvt.u32.u64 %0, t; }" : "=r"(a) : "l"(p));
    return a;
}
static __device__ __forceinline__ void ldsm4(uint32_t* r, uint32_t addr) {
    asm volatile("ldmatrix.sync.aligned.m8n8.x4.shared.b16 {%0,%1,%2,%3}, [%4];"
        : "=r"(r[0]), "=r"(r[1]), "=r"(r[2]), "=r"(r[3]) : "r"(addr));
}
static __device__ __forceinline__ void mma16816(float* c, const uint32_t* a, const uint32_t* b) {
    asm volatile("mma.sync.aligned.m16n8k16.row.col.f32.bf16.bf16.f32 "
        "{%0,%1,%2,%3}, {%4,%5,%6,%7}, {%8,%9}, {%0,%1,%2,%3};"
        : "+f"(c[0]), "+f"(c[1]), "+f"(c[2]), "+f"(c[3])
        : "r"(a[0]), "r"(a[1]), "r"(a[2]), "r"(a[3]), "r"(b[0]), "r"(b[1]));
}
#define CP_ASYNC(dst, src) \
    asm volatile("cp.async.cg.shared.global [%0], [%1], 16;" :: "r"(dst), "l"(src) : "memory")
#define CP_COMMIT() asm volatile("cp.async.commit_group;" ::: "memory")

static __device__ __forceinline__ void split_bf16(float v, __nv_bfloat16& h, __nv_bfloat16& l) {
    h = __float2bfloat16(v);
    l = __float2bfloat16(v - __bfloat162float(h));
}

// ---------------- weight split+transpose: [K,N] f32 -> [N,K] bf16 hi/lo ------
__global__ void wconv_kernel(const float* __restrict__ W, __nv_bfloat16* __restrict__ Whi,
                             __nv_bfloat16* __restrict__ Wlo, int K, int N)
{
    __shared__ float tile[32][33];
    int l = blockIdx.z;
    const float* Wl = W + (size_t)l * K * N;
    __nv_bfloat16* Oh = Whi + (size_t)l * K * N;
    __nv_bfloat16* Ol = Wlo + (size_t)l * K * N;
    int n0 = blockIdx.x * 32, k0 = blockIdx.y * 32;
    int tx = threadIdx.x, ty = threadIdx.y;
    for (int i = ty; i < 32; i += 8)
        tile[i][tx] = Wl[(size_t)(k0 + i) * N + n0 + tx];
    __syncthreads();
    for (int i = ty; i < 32; i += 8) {
        float v = tile[tx][i];
        __nv_bfloat16 h, lo;
        split_bf16(v, h, lo);
        Oh[(size_t)(n0 + i) * K + k0 + tx] = h;
        Ol[(size_t)(n0 + i) * K + k0 + tx] = lo;
    }
}

// ---------------- bf16x3 split MMA GEMM --------------------------------------
// out[M,N] = (Ah+Al)[M,K] @ (Bh+Bl)[N,K]^T (+bias)(+res)(+gelu)
// block tile 128x128, k-slab 64, double buffered cp.async.
__global__ __launch_bounds__(256, 1) void mma_gemm(
    const __nv_bfloat16* __restrict__ Ah, const __nv_bfloat16* __restrict__ Al,
    const __nv_bfloat16* __restrict__ Bh, const __nv_bfloat16* __restrict__ Bl,
    const float* __restrict__ bias, const float* __restrict__ res,
    float* __restrict__ outF, __nv_bfloat16* __restrict__ outHi,
    __nv_bfloat16* __restrict__ outLo, int N, int K, int act)
{
    extern __shared__ char smem[];
    const int tid = threadIdx.x;
    const int lane = tid & 31, wid = tid >> 5;
    const int wm = wid & 1, wn = wid >> 1;
    const int m0 = blockIdx.y * 128, n0 = blockIdx.x * 128;
    const int NS = K >> 6;

    // fill k-slab (64 wide) into stage: Ah@0 Al@16K Bh@32K Bl@48K, SW128 rows
    auto fill = [&](int st, int k0) {
        uint32_t sa = s2u(smem) + st * 65536;
#pragma unroll
        for (int i = 0; i < 4; i++) {
            int idx = tid + i * 256;
            int r = idx >> 3, c = idx & 7;
            int off = r * 128 + c * 16;
            int sw = off ^ ((off >> 3) & 0x70);
            size_t gA = (size_t)(m0 + r) * K + k0 + c * 8;
            size_t gB = (size_t)(n0 + r) * K + k0 + c * 8;
            CP_ASYNC(sa + sw,         Ah + gA);
            CP_ASYNC(sa + 16384 + sw, Al + gA);
            CP_ASYNC(sa + 32768 + sw, Bh + gB);
            CP_ASYNC(sa + 49152 + sw, Bl + gB);
        }
        CP_COMMIT();
    };

    float acc[4][4][4];
#pragma unroll
    for (int i = 0; i < 4; i++)
#pragma unroll
        for (int j = 0; j < 4; j++)
#pragma unroll
            for (int k = 0; k < 4; k++) acc[i][j][k] = 0.f;

    fill(0, 0);

    // per-lane ldmatrix coordinates (within 128B swizzled rows)
    const int a_row = wm * 64 + (lane & 15);
    const int a_kb  = (lane >> 4) * 16;
    const int b_row = wn * 32 + (lane & 7) + ((lane >> 4) << 3);
    const int b_kb  = ((lane >> 3) & 1) * 16;

    for (int slab = 0; slab < NS; slab++) {
        if (slab + 1 < NS) {
            fill((slab + 1) & 1, (slab + 1) * 64);
            asm volatile("cp.async.wait_group 1;" ::: "memory");
        } else {
            asm volatile("cp.async.wait_group 0;" ::: "memory");
        }
        __syncthreads();
        uint32_t sa = s2u(smem) + (slab & 1) * 65536;
#pragma unroll
        for (int ks = 0; ks < 4; ks++) {
            uint32_t ahf[4][4], alf[4][4], bhf[4][2], blf[4][2];
#pragma unroll
            for (int mt = 0; mt < 4; mt++) {
                int off = (a_row + mt * 16) * 128 + ks * 32 + a_kb;
                int sw = off ^ ((off >> 3) & 0x70);
                ldsm4(ahf[mt], sa + sw);
                ldsm4(alf[mt], sa + 16384 + sw);
            }
#pragma unroll
            for (int np = 0; np < 2; np++) {
                int off = (b_row + np * 16) * 128 + ks * 32 + b_kb;
                int sw = off ^ ((off >> 3) & 0x70);
                uint32_t t[4];
                ldsm4(t, sa + 32768 + sw);
                bhf[np*2][0] = t[0]; bhf[np*2][1] = t[1];
                bhf[np*2+1][0] = t[2]; bhf[np*2+1][1] = t[3];
                ldsm4(t, sa + 49152 + sw);
                blf[np*2][0] = t[0]; blf[np*2][1] = t[1];
                blf[np*2+1][0] = t[2]; blf[np*2+1][1] = t[3];
            }
#pragma unroll
            for (int mt = 0; mt < 4; mt++)
#pragma unroll
                for (int nt = 0; nt < 4; nt++) {
                    mma16816(acc[mt][nt], ahf[mt], bhf[nt]);
                    mma16816(acc[mt][nt], ahf[mt], blf[nt]);
                    mma16816(acc[mt][nt], alf[mt], bhf[nt]);
                }
        }
        __syncthreads();
    }

    // epilogue: fragments -> smem (pitch 132) -> coalesced global
    float* sOut = (float*)smem;
#pragma unroll
    for (int mt = 0; mt < 4; mt++)
#pragma unroll
        for (int nt = 0; nt < 4; nt++) {
            int m = wm * 64 + mt * 16 + (lane >> 2);
            int n = wn * 32 + nt * 8 + (lane & 3) * 2;
            *(float2*)&sOut[m * 132 + n]       = make_float2(acc[mt][nt][0], acc[mt][nt][1]);
            *(float2*)&sOut[(m + 8) * 132 + n] = make_float2(acc[mt][nt][2], acc[mt][nt][3]);
        }
    __syncthreads();

#pragma unroll
    for (int it = 0; it < 16; it++) {
        int idx = tid + it * 256;
        int row = idx >> 5, c4 = (idx & 31) * 4;
        int n = n0 + c4;
        float v[4];
#pragma unroll
        for (int j = 0; j < 4; j++) v[j] = sOut[row * 132 + c4 + j] + bias[n + j];
        size_t go = (size_t)(m0 + row) * N + n;
        if (res) {
            float4 rv = *(const float4*)(res + go);
            v[0] += rv.x; v[1] += rv.y; v[2] += rv.z; v[3] += rv.w;
        }
        if (act == 1) {
#pragma unroll
            for (int j = 0; j < 4; j++)
                v[j] = 0.5f * v[j] * (1.f + erff(v[j] * 0.70710678118654752f));
        }
        if (outF) {
            *(float4*)(outF + go) = make_float4(v[0], v[1], v[2], v[3]);
        } else {
            __nv_bfloat16 h[4], l[4];
#pragma unroll
            for (int j = 0; j < 4; j++) split_bf16(v[j], h[j], l[j]);
            *(uint2*)(outHi + go) = *(uint2*)h;
            *(uint2*)(outLo + go) = *(uint2*)l;
        }
    }
}

// ---------------- patch embed ------------------------------------------------
__global__ __launch_bounds__(256) void embed_kernel(
    const float* __restrict__ x, const float* __restrict__ w,
    const float* __restrict__ bias, float* __restrict__ out)
{
    int s = blockIdx.x, b = blockIdx.y, tid = threadIdx.x;
    __shared__ float patch[768];
    int sp    = (s < 400) ? s : s - 400;
    int choff = (s < 400) ? 0 : 3;
    int gh = sp / 20, gw = sp % 20;
    for (int j = tid; j < 768; j += 256) {
        int ci = j >> 8, ph = (j >> 4) & 15, pw = j & 15;
        patch[j] = x[(((size_t)b * 6 + choff + ci) * 320 + gh * 16 + ph) * 320 + gw * 16 + pw];
    }
    __syncthreads();
#pragma unroll
    for (int u = 0; u < 3; u++) {
        int c = tid + u * 256;
        const float4* wr = (const float4*)(w + (size_t)c * 768);
        const float4* pp = (const float4*)patch;
        float acc = bias[c];
#pragma unroll 8
        for (int j4 = 0; j4 < 192; j4++) {
            float4 wv = wr[j4], pv = pp[j4];
            acc += wv.x * pv.x + wv.y * pv.y + wv.z * pv.z + wv.w * pv.w;
        }
        out[((size_t)(b * 800 + s)) * 768 + c] = acc;
    }
}

// ---------------- layernorm (float out) --------------------------------------
__global__ __launch_bounds__(256) void ln_kernel(
    const float* __restrict__ in, float* __restrict__ out,
    const float* __restrict__ g, const float* __restrict__ bta)
{
    int row = blockIdx.x, tid = threadIdx.x;
    const float* x = in + (size_t)row * C;
    __shared__ float red[256];
    float s = 0.f;
    for (int i = tid; i < C; i += 256) s += x[i];
    red[tid] = s; __syncthreads();
    for (int st = 128; st > 0; st >>= 1) { if (tid < st) red[tid] += red[tid + st]; __syncthreads(); }
    float mean = red[0] / (float)C;
    __syncthreads();
    float v = 0.f;
    for (int i = tid; i < C; i += 256) { float d = x[i] - mean; v += d * d; }
    red[tid] = v; __syncthreads();
    for (int st = 128; st > 0; st >>= 1) { if (tid < st) red[tid] += red[tid + st]; __syncthreads(); }
    float inv = rsqrtf(red[0] / (float)C + 1e-6f);
    float* o = out + (size_t)row * C;
    for (int i = tid; i < C; i += 256) o[i] = (x[i] - mean) * inv * g[i] + bta[i];
}

// ---------------- layernorm with fused bf16 split output ---------------------
__global__ __launch_bounds__(256) void ln_split_kernel(
    const float* __restrict__ in, __nv_bfloat16* __restrict__ hi,
    __nv_bfloat16* __restrict__ lo,
    const float* __restrict__ g, const float* __restrict__ bta)
{
    int row = blockIdx.x, tid = threadIdx.x;
    const float* x = in + (size_t)row * C;
    __shared__ float red[256];
    float s = 0.f;
    for (int i = tid; i < C; i += 256) s += x[i];
    red[tid] = s; __syncthreads();
    for (int st = 128; st > 0; st >>= 1) { if (tid < st) red[tid] += red[tid + st]; __syncthreads(); }
    float mean = red[0] / (float)C;
    __syncthreads();
    float v = 0.f;
    for (int i = tid; i < C; i += 256) { float d = x[i] - mean; v += d * d; }
    red[tid] = v; __syncthreads();
    for (int st = 128; st > 0; st >>= 1) { if (tid < st) red[tid] += red[tid + st]; __syncthreads(); }
    float inv = rsqrtf(red[0] / (float)C + 1e-6f);
    for (int i = tid; i < C; i += 256) {
        float val = (x[i] - mean) * inv * g[i] + bta[i];
        __nv_bfloat16 h, l;
        split_bf16(val, h, l);
        hi[(size_t)row * C + i] = h;
        lo[(size_t)row * C + i] = l;
    }
}

// ---------------- RoPE -------------------------------------------------------
__global__ __launch_bounds__(256) void rope_kernel(float* __restrict__ qkv,
                                                   float* __restrict__ kT)
{
    int idx = blockIdx.x * blockDim.x + threadIdx.x;
    const int TOT = B * S * NH * (DH / 2);
    if (idx >= TOT) return;
    int d2 = idx & 31;
    int h  = (idx >> 5) % NH;
    int bs = idx / (32 * NH);
    int s  = bs % S;
    int b  = bs / S;
    float* qp = qkv + (size_t)bs * (3 * C) + h * DH;
    float* kp = qp + C;
    int d0 = 2 * d2, d1 = 2 * d2 + 1;
    float a0 = (float)s * powf(10000.f, -(float)(d0 & 31) / 32.f);
    float a1 = (float)s * powf(10000.f, -(float)(d1 & 31) / 32.f);
    float c0 = cosf(a0), s0 = sinf(a0);
    float c1 = cosf(a1), s1 = sinf(a1);
    float q0 = qp[d0], q1 = qp[d1];
    qp[d0] = q0 * c0 - q1 * s0;
    qp[d1] = q1 * c1 + q0 * s1;
    float k0 = kp[d0], k1 = kp[d1];
    float kn0 = k0 * c0 - k1 * s0;
    float kn1 = k1 * c1 + k0 * s1;
    int bh = b * NH + h;
    kT[((size_t)bh * DH + d0) * S + s] = kn0;
    kT[((size_t)bh * DH + d1) * S + s] = kn1;
}

// ---------------- attention (fused bf16 split output) ------------------------
__global__ __launch_bounds__(256) void attn_kernel(const float* __restrict__ qkv,
                                                   const float* __restrict__ kT,
                                                   __nv_bfloat16* __restrict__ ohi,
                                                   __nv_bfloat16* __restrict__ olo)
{
    int s = blockIdx.x, bh = blockIdx.y;
    int b = bh / NH, h = bh % NH;
    int tid = threadIdx.x;
    __shared__ float sc[S];
    __shared__ float red[256];
    __shared__ float qv[DH];
    const float* qrow = qkv + ((size_t)(b * S + s)) * (3 * C) + h * DH;
    if (tid < DH) qv[tid] = qrow[tid];
    __syncthreads();

    const float* kbase = kT + (size_t)bh * DH * S;
    float lmax = -1e30f;
    for (int t = tid; t < S; t += 256) {
        float acc = 0.f;
#pragma unroll
        for (int d = 0; d < DH; d++) acc += qv[d] * kbase[(size_t)d * S + t];
        acc *= 0.125f;
        sc[t] = acc;
        lmax = fmaxf(lmax, acc);
    }
    red[tid] = lmax; __syncthreads();
    for (int st = 128; st > 0; st >>= 1) { if (tid < st) red[tid] = fmaxf(red[tid], red[tid + st]); __syncthreads(); }
    float m = red[0]; __syncthreads();
    float lsum = 0.f;
    for (int t = tid; t < S; t += 256) { float p = expf(sc[t] - m); sc[t] = p; lsum += p; }
    red[tid] = lsum; __syncthreads();
    for (int st = 128; st > 0; st >>= 1) { if (tid < st) red[tid] += red[tid + st]; __syncthreads(); }
    float inv = 1.f / red[0];
    __syncthreads();

    int d = tid & 63, c = tid >> 6;
    float acc = 0.f;
    const float* vbase = qkv + 2 * C + h * DH + d;
    for (int t = c * 200; t < (c + 1) * 200; t++)
        acc += sc[t] * vbase[((size_t)(b * S + t)) * (3 * C)];
    red[tid] = acc; __syncthreads();
    if (tid < 64) {
        float r = (red[tid] + red[tid + 64] + red[tid + 128] + red[tid + 192]) * inv;
        __nv_bfloat16 hi, lo;
        split_bf16(r, hi, lo);
        size_t oi = ((size_t)(b * S + s)) * C + h * DH + tid;
        ohi[oi] = hi;
        olo[oi] = lo;
    }
}

// ---------------- host orchestration ----------------------------------------
extern "C" void kernel_launch(void* const* d_in, const int* in_sizes, int n_in,
                              void* d_out, int out_size)
{
    const float* x      = (const float*)d_in[0];
    const float* conv_w = (const float*)d_in[1];
    const float* conv_b = (const float*)d_in[2];
    const float* ln1_g  = (const float*)d_in[3];
    const float* ln1_b  = (const float*)d_in[4];
    const float* qkv_w  = (const float*)d_in[5];
    const float* qkv_b  = (const float*)d_in[6];
    const float* proj_w = (const float*)d_in[7];
    const float* proj_b = (const float*)d_in[8];
    const float* ln2_g  = (const float*)d_in[9];
    const float* ln2_b  = (const float*)d_in[10];
    const float* fc1_w  = (const float*)d_in[11];
    const float* fc1_b  = (const float*)d_in[12];
    const float* fc2_w  = (const float*)d_in[13];
    const float* fc2_b  = (const float*)d_in[14];
    const float* lnf_g  = (const float*)d_in[15];
    const float* lnf_b  = (const float*)d_in[16];
    float* out = (float*)d_out;

    float *h_p, *qkv_p, *kT_p;
    cudaGetSymbolAddress((void**)&h_p,   g_h);
    cudaGetSymbolAddress((void**)&qkv_p, g_qkv);
    cudaGetSymbolAddress((void**)&kT_p,  g_kT);

    __nv_bfloat16 *wq_h, *wq_l, *wp_h, *wp_l, *w1_h, *w1_l, *w2_h, *w2_l;
    __nv_bfloat16 *ah, *al, *h1h, *h1l;
    cudaGetSymbolAddress((void**)&wq_h, g_wq_h);
    cudaGetSymbolAddress((void**)&wq_l, g_wq_l);
    cudaGetSymbolAddress((void**)&wp_h, g_wp_h);
    cudaGetSymbolAddress((void**)&wp_l, g_wp_l);
    cudaGetSymbolAddress((void**)&w1_h, g_w1_h);
    cudaGetSymbolAddress((void**)&w1_l, g_w1_l);
    cudaGetSymbolAddress((void**)&w2_h, g_w2_h);
    cudaGetSymbolAddress((void**)&w2_l, g_w2_l);
    cudaGetSymbolAddress((void**)&ah,  g_ah);
    cudaGetSymbolAddress((void**)&al,  g_al);
    cudaGetSymbolAddress((void**)&h1h, g_h1h);
    cudaGetSymbolAddress((void**)&h1l, g_h1l);

    const int SMEM = 131072;  // 2 x 64KB stages; epilogue reuses it
    cudaFuncSetAttribute(mma_gemm, cudaFuncAttributeMaxDynamicSharedMemorySize, SMEM);

    // weight split+transpose (captured; runs per replay, ~0.15ms)
    wconv_kernel<<<dim3(2304/32, 768/32, DEPTH), dim3(32, 8)>>>(qkv_w, wq_h, wq_l, 768, 2304);
    wconv_kernel<<<dim3(768/32,  768/32, DEPTH), dim3(32, 8)>>>(proj_w, wp_h, wp_l, 768, 768);
    wconv_kernel<<<dim3(3072/32, 768/32, DEPTH), dim3(32, 8)>>>(fc1_w, w1_h, w1_l, 768, 3072);
    wconv_kernel<<<dim3(768/32, 3072/32, DEPTH), dim3(32, 8)>>>(fc2_w, w2_h, w2_l, 3072, 768);

    embed_kernel<<<dim3(S, B), 256>>>(x, conv_w, conv_b, h_p);

    const int ropeN = B * S * NH * (DH / 2);
    for (int l = 0; l < DEPTH; l++) {
        ln_split_kernel<<<ROWS, 256>>>(h_p, ah, al, ln1_g + l * C, ln1_b + l * C);
        mma_gemm<<<dim3(2304/128, ROWS/128), 256, SMEM>>>(
            ah, al, wq_h + (size_t)l * 2304 * 768, wq_l + (size_t)l * 2304 * 768,
            qkv_b + (size_t)l * 3 * C, nullptr, qkv_p, nullptr, nullptr, 2304, 768, 0);
        rope_kernel<<<(ropeN + 255) / 256, 256>>>(qkv_p, kT_p);
        attn_kernel<<<dim3(S, B * NH), 256>>>(qkv_p, kT_p, ah, al);
        mma_gemm<<<dim3(768/128, ROWS/128), 256, SMEM>>>(
            ah, al, wp_h + (size_t)l * 768 * 768, wp_l + (size_t)l * 768 * 768,
            proj_b + (size_t)l * C, h_p, h_p, nullptr, nullptr, 768, 768, 0);
        ln_split_kernel<<<ROWS, 256>>>(h_p, ah, al, ln2_g + l * C, ln2_b + l * C);
        mma_gemm<<<dim3(3072/128, ROWS/128), 256, SMEM>>>(
            ah, al, w1_h + (size_t)l * 3072 * 768, w1_l + (size_t)l * 3072 * 768,
            fc1_b + (size_t)l * HID, nullptr, nullptr, h1h, h1l, 3072, 768, 1);
        mma_gemm<<<dim3(768/128, ROWS/128), 256, SMEM>>>(
            h1h, h1l, w2_h + (size_t)l * 768 * 3072, w2_l + (size_t)l * 768 * 3072,
            fc2_b + (size_t)l * C, h_p, h_p, nullptr, nullptr, 768, 3072, 0);
    }
    ln_kernel<<<ROWS, 256>>>(h_p, out, lnf_g, lnf_b);
}

// round 4
// speedup vs baseline: 2.1370x; 1.2985x over previous
#include <cuda_runtime.h>
#include <cuda_bf16.h>
#include <math.h>
#include <stdint.h>

#define B 4
#define S 800
#define C 768
#define NH 12
#define DH 64
#define HID 3072
#define DEPTH 12
#define ROWS (B*S)   // 3200

// ---------------- scratch (static device globals; no runtime alloc) ----------
__device__ float g_h  [ROWS * C];
__device__ float g_qkv[ROWS * 3 * C];

// bf16 split weights, transposed to [N,K] per layer
__device__ __nv_bfloat16 g_wq_h[DEPTH * 2304 * 768];
__device__ __nv_bfloat16 g_wq_l[DEPTH * 2304 * 768];
__device__ __nv_bfloat16 g_wp_h[DEPTH * 768 * 768];
__device__ __nv_bfloat16 g_wp_l[DEPTH * 768 * 768];
__device__ __nv_bfloat16 g_w1_h[DEPTH * 3072 * 768];
__device__ __nv_bfloat16 g_w1_l[DEPTH * 3072 * 768];
__device__ __nv_bfloat16 g_w2_h[DEPTH * 768 * 3072];
__device__ __nv_bfloat16 g_w2_l[DEPTH * 768 * 3072];
// bf16 split activations
__device__ __nv_bfloat16 g_ah [ROWS * C];
__device__ __nv_bfloat16 g_al [ROWS * C];
__device__ __nv_bfloat16 g_h1h[ROWS * HID];
__device__ __nv_bfloat16 g_h1l[ROWS * HID];

// ---------------- helpers ------------------------------------------------
static __device__ __forceinline__ uint32_t s2u(const void* p) {
    uint32_t a;
    asm("{ .reg .u64 t; cvta.to.shared.u64 t, %1; cvt.u32.u64 %0, t; }" : "=r"(a) : "l"(p));
    return a;
}
static __device__ __forceinline__ void ldsm4(uint32_t* r, uint32_t addr) {
    asm volatile("ldmatrix.sync.aligned.m8n8.x4.shared.b16 {%0,%1,%2,%3}, [%4];"
        : "=r"(r[0]), "=r"(r[1]), "=r"(r[2]), "=r"(r[3]) : "r"(addr));
}
static __device__ __forceinline__ void mma16816(float* c, const uint32_t* a, const uint32_t* b) {
    asm volatile("mma.sync.aligned.m16n8k16.row.col.f32.bf16.bf16.f32 "
        "{%0,%1,%2,%3}, {%4,%5,%6,%7}, {%8,%9}, {%0,%1,%2,%3};"
        : "+f"(c[0]), "+f"(c[1]), "+f"(c[2]), "+f"(c[3])
        : "r"(a[0]), "r"(a[1]), "r"(a[2]), "r"(a[3]), "r"(b[0]), "r"(b[1]));
}
#define CP_ASYNC(dst, src) \
    asm volatile("cp.async.cg.shared.global [%0], [%1], 16;" :: "r"(dst), "l"(src) : "memory")
#define CP_COMMIT() asm volatile("cp.async.commit_group;" ::: "memory")

static __device__ __forceinline__ void split_bf16(float v, __nv_bfloat16& h, __nv_bfloat16& l) {
    h = __float2bfloat16(v);
    l = __float2bfloat16(v - __bfloat162float(h));
}

// ---------------- weight split+transpose: [K,N] f32 -> [N,K] bf16 hi/lo ------
__global__ void wconv_kernel(const float* __restrict__ W, __nv_bfloat16* __restrict__ Whi,
                             __nv_bfloat16* __restrict__ Wlo, int K, int N)
{
    __shared__ float tile[32][33];
    int l = blockIdx.z;
    const float* Wl = W + (size_t)l * K * N;
    __nv_bfloat16* Oh = Whi + (size_t)l * K * N;
    __nv_bfloat16* Ol = Wlo + (size_t)l * K * N;
    int n0 = blockIdx.x * 32, k0 = blockIdx.y * 32;
    int tx = threadIdx.x, ty = threadIdx.y;
    for (int i = ty; i < 32; i += 8)
        tile[i][tx] = Wl[(size_t)(k0 + i) * N + n0 + tx];
    __syncthreads();
    for (int i = ty; i < 32; i += 8) {
        float v = tile[tx][i];
        __nv_bfloat16 h, lo;
        split_bf16(v, h, lo);
        Oh[(size_t)(n0 + i) * K + k0 + tx] = h;
        Ol[(size_t)(n0 + i) * K + k0 + tx] = lo;
    }
}

// ---------------- bf16x3 split MMA GEMM --------------------------------------
__global__ __launch_bounds__(256, 1) void mma_gemm(
    const __nv_bfloat16* __restrict__ Ah, const __nv_bfloat16* __restrict__ Al,
    const __nv_bfloat16* __restrict__ Bh, const __nv_bfloat16* __restrict__ Bl,
    const float* __restrict__ bias, const float* __restrict__ res,
    float* __restrict__ outF, __nv_bfloat16* __restrict__ outHi,
    __nv_bfloat16* __restrict__ outLo, int N, int K, int act)
{
    extern __shared__ char smem[];
    const int tid = threadIdx.x;
    const int lane = tid & 31, wid = tid >> 5;
    const int wm = wid & 1, wn = wid >> 1;
    const int m0 = blockIdx.y * 128, n0 = blockIdx.x * 128;
    const int NS = K >> 6;

    auto fill = [&](int st, int k0) {
        uint32_t sa = s2u(smem) + st * 65536;
#pragma unroll
        for (int i = 0; i < 4; i++) {
            int idx = tid + i * 256;
            int r = idx >> 3, c = idx & 7;
            int off = r * 128 + c * 16;
            int sw = off ^ ((off >> 3) & 0x70);
            size_t gA = (size_t)(m0 + r) * K + k0 + c * 8;
            size_t gB = (size_t)(n0 + r) * K + k0 + c * 8;
            CP_ASYNC(sa + sw,         Ah + gA);
            CP_ASYNC(sa + 16384 + sw, Al + gA);
            CP_ASYNC(sa + 32768 + sw, Bh + gB);
            CP_ASYNC(sa + 49152 + sw, Bl + gB);
        }
        CP_COMMIT();
    };

    float acc[4][4][4];
#pragma unroll
    for (int i = 0; i < 4; i++)
#pragma unroll
        for (int j = 0; j < 4; j++)
#pragma unroll
            for (int k = 0; k < 4; k++) acc[i][j][k] = 0.f;

    fill(0, 0);

    const int a_row = wm * 64 + (lane & 15);
    const int a_kb  = (lane >> 4) * 16;
    const int b_row = wn * 32 + (lane & 7) + ((lane >> 4) << 3);
    const int b_kb  = ((lane >> 3) & 1) * 16;

    for (int slab = 0; slab < NS; slab++) {
        if (slab + 1 < NS) {
            fill((slab + 1) & 1, (slab + 1) * 64);
            asm volatile("cp.async.wait_group 1;" ::: "memory");
        } else {
            asm volatile("cp.async.wait_group 0;" ::: "memory");
        }
        __syncthreads();
        uint32_t sa = s2u(smem) + (slab & 1) * 65536;
#pragma unroll
        for (int ks = 0; ks < 4; ks++) {
            uint32_t ahf[4][4], alf[4][4], bhf[4][2], blf[4][2];
#pragma unroll
            for (int mt = 0; mt < 4; mt++) {
                int off = (a_row + mt * 16) * 128 + ks * 32 + a_kb;
                int sw = off ^ ((off >> 3) & 0x70);
                ldsm4(ahf[mt], sa + sw);
                ldsm4(alf[mt], sa + 16384 + sw);
            }
#pragma unroll
            for (int np = 0; np < 2; np++) {
                int off = (b_row + np * 16) * 128 + ks * 32 + b_kb;
                int sw = off ^ ((off >> 3) & 0x70);
                uint32_t t[4];
                ldsm4(t, sa + 32768 + sw);
                bhf[np*2][0] = t[0]; bhf[np*2][1] = t[1];
                bhf[np*2+1][0] = t[2]; bhf[np*2+1][1] = t[3];
                ldsm4(t, sa + 49152 + sw);
                blf[np*2][0] = t[0]; blf[np*2][1] = t[1];
                blf[np*2+1][0] = t[2]; blf[np*2+1][1] = t[3];
            }
#pragma unroll
            for (int mt = 0; mt < 4; mt++)
#pragma unroll
                for (int nt = 0; nt < 4; nt++) {
                    mma16816(acc[mt][nt], ahf[mt], bhf[nt]);
                    mma16816(acc[mt][nt], ahf[mt], blf[nt]);
                    mma16816(acc[mt][nt], alf[mt], bhf[nt]);
                }
        }
        __syncthreads();
    }

    float* sOut = (float*)smem;
#pragma unroll
    for (int mt = 0; mt < 4; mt++)
#pragma unroll
        for (int nt = 0; nt < 4; nt++) {
            int m = wm * 64 + mt * 16 + (lane >> 2);
            int n = wn * 32 + nt * 8 + (lane & 3) * 2;
            *(float2*)&sOut[m * 132 + n]       = make_float2(acc[mt][nt][0], acc[mt][nt][1]);
            *(float2*)&sOut[(m + 8) * 132 + n] = make_float2(acc[mt][nt][2], acc[mt][nt][3]);
        }
    __syncthreads();

#pragma unroll
    for (int it = 0; it < 16; it++) {
        int idx = tid + it * 256;
        int row = idx >> 5, c4 = (idx & 31) * 4;
        int n = n0 + c4;
        float v[4];
#pragma unroll
        for (int j = 0; j < 4; j++) v[j] = sOut[row * 132 + c4 + j] + bias[n + j];
        size_t go = (size_t)(m0 + row) * N + n;
        if (res) {
            float4 rv = *(const float4*)(res + go);
            v[0] += rv.x; v[1] += rv.y; v[2] += rv.z; v[3] += rv.w;
        }
        if (act == 1) {
#pragma unroll
            for (int j = 0; j < 4; j++)
                v[j] = 0.5f * v[j] * (1.f + erff(v[j] * 0.70710678118654752f));
        }
        if (outF) {
            *(float4*)(outF + go) = make_float4(v[0], v[1], v[2], v[3]);
        } else {
            __nv_bfloat16 h[4], l[4];
#pragma unroll
            for (int j = 0; j < 4; j++) split_bf16(v[j], h[j], l[j]);
            *(uint2*)(outHi + go) = *(uint2*)h;
            *(uint2*)(outLo + go) = *(uint2*)l;
        }
    }
}

// ---------------- patch embed ------------------------------------------------
__global__ __launch_bounds__(256) void embed_kernel(
    const float* __restrict__ x, const float* __restrict__ w,
    const float* __restrict__ bias, float* __restrict__ out)
{
    int s = blockIdx.x, b = blockIdx.y, tid = threadIdx.x;
    __shared__ float patch[768];
    int sp    = (s < 400) ? s : s - 400;
    int choff = (s < 400) ? 0 : 3;
    int gh = sp / 20, gw = sp % 20;
    for (int j = tid; j < 768; j += 256) {
        int ci = j >> 8, ph = (j >> 4) & 15, pw = j & 15;
        patch[j] = x[(((size_t)b * 6 + choff + ci) * 320 + gh * 16 + ph) * 320 + gw * 16 + pw];
    }
    __syncthreads();
#pragma unroll
    for (int u = 0; u < 3; u++) {
        int c = tid + u * 256;
        const float4* wr = (const float4*)(w + (size_t)c * 768);
        const float4* pp = (const float4*)patch;
        float acc = bias[c];
#pragma unroll 8
        for (int j4 = 0; j4 < 192; j4++) {
            float4 wv = wr[j4], pv = pp[j4];
            acc += wv.x * pv.x + wv.y * pv.y + wv.z * pv.z + wv.w * pv.w;
        }
        out[((size_t)(b * 800 + s)) * 768 + c] = acc;
    }
}

// ---------------- layernorm (float out) --------------------------------------
__global__ __launch_bounds__(256) void ln_kernel(
    const float* __restrict__ in, float* __restrict__ out,
    const float* __restrict__ g, const float* __restrict__ bta)
{
    int row = blockIdx.x, tid = threadIdx.x;
    const float* x = in + (size_t)row * C;
    __shared__ float red[256];
    float s = 0.f;
    for (int i = tid; i < C; i += 256) s += x[i];
    red[tid] = s; __syncthreads();
    for (int st = 128; st > 0; st >>= 1) { if (tid < st) red[tid] += red[tid + st]; __syncthreads(); }
    float mean = red[0] / (float)C;
    __syncthreads();
    float v = 0.f;
    for (int i = tid; i < C; i += 256) { float d = x[i] - mean; v += d * d; }
    red[tid] = v; __syncthreads();
    for (int st = 128; st > 0; st >>= 1) { if (tid < st) red[tid] += red[tid + st]; __syncthreads(); }
    float inv = rsqrtf(red[0] / (float)C + 1e-6f);
    float* o = out + (size_t)row * C;
    for (int i = tid; i < C; i += 256) o[i] = (x[i] - mean) * inv * g[i] + bta[i];
}

// ---------------- layernorm with fused bf16 split output ---------------------
__global__ __launch_bounds__(256) void ln_split_kernel(
    const float* __restrict__ in, __nv_bfloat16* __restrict__ hi,
    __nv_bfloat16* __restrict__ lo,
    const float* __restrict__ g, const float* __restrict__ bta)
{
    int row = blockIdx.x, tid = threadIdx.x;
    const float* x = in + (size_t)row * C;
    __shared__ float red[256];
    float s = 0.f;
    for (int i = tid; i < C; i += 256) s += x[i];
    red[tid] = s; __syncthreads();
    for (int st = 128; st > 0; st >>= 1) { if (tid < st) red[tid] += red[tid + st]; __syncthreads(); }
    float mean = red[0] / (float)C;
    __syncthreads();
    float v = 0.f;
    for (int i = tid; i < C; i += 256) { float d = x[i] - mean; v += d * d; }
    red[tid] = v; __syncthreads();
    for (int st = 128; st > 0; st >>= 1) { if (tid < st) red[tid] += red[tid + st]; __syncthreads(); }
    float inv = rsqrtf(red[0] / (float)C + 1e-6f);
    for (int i = tid; i < C; i += 256) {
        float val = (x[i] - mean) * inv * g[i] + bta[i];
        __nv_bfloat16 h, l;
        split_bf16(val, h, l);
        hi[(size_t)row * C + i] = h;
        lo[(size_t)row * C + i] = l;
    }
}

// ---------------- RoPE: rotate q and k in place ------------------------------
__global__ __launch_bounds__(256) void rope_kernel(float* __restrict__ qkv)
{
    int idx = blockIdx.x * blockDim.x + threadIdx.x;
    const int TOT = B * S * NH * (DH / 2);
    if (idx >= TOT) return;
    int d2 = idx & 31;
    int h  = (idx >> 5) % NH;
    int bs = idx / (32 * NH);
    int s  = bs % S;
    float* qp = qkv + (size_t)bs * (3 * C) + h * DH;
    float* kp = qp + C;
    int d0 = 2 * d2, d1 = 2 * d2 + 1;
    float a0 = (float)s * powf(10000.f, -(float)(d0 & 31) / 32.f);
    float a1 = (float)s * powf(10000.f, -(float)(d1 & 31) / 32.f);
    float c0 = cosf(a0), s0 = sinf(a0);
    float c1 = cosf(a1), s1 = sinf(a1);
    float q0 = qp[d0], q1 = qp[d1];
    qp[d0] = q0 * c0 - q1 * s0;
    qp[d1] = q1 * c1 + q0 * s1;
    float k0 = kp[d0], k1 = kp[d1];
    kp[d0] = k0 * c0 - k1 * s0;
    kp[d1] = k1 * c1 + k0 * s1;
}

// ---------------- flash attention (fp32), fused bf16 split output ------------
// QT=80 queries/block, stream keys in KT=80 tiles. 320 threads.
// thread t: row q = t/4, seg = t%4. scores: keys k = seg + 4*kk (kk<20).
//           O: dims d = seg*4 + 16*j + i (j<4, i<4).
#define QT 80
#define KT 80
#define ATT_THREADS 320
#define QK_PITCH 68   // floats per row (pad 64 -> 68)
#define P_PITCH  84
__global__ __launch_bounds__(ATT_THREADS, 2) void attn_kernel(
    const float* __restrict__ qkv,
    __nv_bfloat16* __restrict__ ohi, __nv_bfloat16* __restrict__ olo)
{
    extern __shared__ char smem_raw[];
    float* sQ = (float*)smem_raw;                       // QT x QK_PITCH
    float* sK = sQ + QT * QK_PITCH;                     // KT x QK_PITCH
    float* sV = sK + KT * QK_PITCH;                     // KT x QK_PITCH
    float* sP = sV + KT * QK_PITCH;                     // QT x P_PITCH

    const int qt = blockIdx.x, bh = blockIdx.y;
    const int b = bh / NH, h = bh % NH;
    const int tid = threadIdx.x;
    const int q = tid >> 2, seg = tid & 3;
    const int s0 = qt * QT;

    // load Q tile (scaled by DH^-0.5)
    for (int i = tid; i < QT * 16; i += ATT_THREADS) {
        int r = i >> 4, c4 = (i & 15) * 4;
        float4 v = *(const float4*)(qkv + (size_t)(b * S + s0 + r) * (3 * C) + h * DH + c4);
        v.x *= 0.125f; v.y *= 0.125f; v.z *= 0.125f; v.w *= 0.125f;
        *(float4*)(sQ + r * QK_PITCH + c4) = v;
    }

    float m = -1e30f, lsum = 0.f;
    float4 O4[4] = {};

    for (int kt = 0; kt < S / KT; kt++) {
        __syncthreads();
        // load K, V tiles
        for (int i = tid; i < KT * 16; i += ATT_THREADS) {
            int r = i >> 4, c4 = (i & 15) * 4;
            size_t base = (size_t)(b * S + kt * KT + r) * (3 * C) + h * DH + c4;
            *(float4*)(sK + r * QK_PITCH + c4) = *(const float4*)(qkv + C + base);
            *(float4*)(sV + r * QK_PITCH + c4) = *(const float4*)(qkv + 2 * C + base);
        }
        __syncthreads();

        // scores for my 20 keys
        float acc[20];
#pragma unroll
        for (int kk = 0; kk < 20; kk++) acc[kk] = 0.f;
#pragma unroll
        for (int d4 = 0; d4 < 16; d4++) {
            float4 q4 = *(float4*)(sQ + q * QK_PITCH + d4 * 4);
#pragma unroll
            for (int kk = 0; kk < 20; kk++) {
                float4 k4 = *(float4*)(sK + (seg + 4 * kk) * QK_PITCH + d4 * 4);
                acc[kk] += q4.x * k4.x + q4.y * k4.y + q4.z * k4.z + q4.w * k4.w;
            }
        }
        float mt = acc[0];
#pragma unroll
        for (int kk = 1; kk < 20; kk++) mt = fmaxf(mt, acc[kk]);
        mt = fmaxf(mt, __shfl_xor_sync(0xffffffffu, mt, 1));
        mt = fmaxf(mt, __shfl_xor_sync(0xffffffffu, mt, 2));
        float new_m = fmaxf(m, mt);
        float fac = __expf(m - new_m);
        float ps = 0.f;
#pragma unroll
        for (int kk = 0; kk < 20; kk++) {
            float p = __expf(acc[kk] - new_m);
            sP[q * P_PITCH + seg + 4 * kk] = p;
            ps += p;
        }
        ps += __shfl_xor_sync(0xffffffffu, ps, 1);
        ps += __shfl_xor_sync(0xffffffffu, ps, 2);
        lsum = lsum * fac + ps;
        m = new_m;
        __syncthreads();

        // O update: O = O*fac + P @ V
#pragma unroll
        for (int j = 0; j < 4; j++) {
            O4[j].x *= fac; O4[j].y *= fac; O4[j].z *= fac; O4[j].w *= fac;
        }
        for (int k = 0; k < KT; k++) {
            float p = sP[q * P_PITCH + k];
            const float* vr = sV + k * QK_PITCH;
#pragma unroll
            for (int j = 0; j < 4; j++) {
                float4 v4 = *(float4*)(vr + seg * 4 + 16 * j);
                O4[j].x += p * v4.x; O4[j].y += p * v4.y;
                O4[j].z += p * v4.z; O4[j].w += p * v4.w;
            }
        }
    }

    float inv = 1.f / lsum;
    size_t orow = (size_t)(b * S + s0 + q) * C + h * DH;
#pragma unroll
    for (int j = 0; j < 4; j++) {
        float v[4] = {O4[j].x * inv, O4[j].y * inv, O4[j].z * inv, O4[j].w * inv};
        __nv_bfloat16 hh[4], ll[4];
#pragma unroll
        for (int i = 0; i < 4; i++) split_bf16(v[i], hh[i], ll[i]);
        size_t oi = orow + seg * 4 + 16 * j;
        *(uint2*)(ohi + oi) = *(uint2*)hh;
        *(uint2*)(olo + oi) = *(uint2*)ll;
    }
}

// ---------------- host orchestration ----------------------------------------
extern "C" void kernel_launch(void* const* d_in, const int* in_sizes, int n_in,
                              void* d_out, int out_size)
{
    const float* x      = (const float*)d_in[0];
    const float* conv_w = (const float*)d_in[1];
    const float* conv_b = (const float*)d_in[2];
    const float* ln1_g  = (const float*)d_in[3];
    const float* ln1_b  = (const float*)d_in[4];
    const float* qkv_w  = (const float*)d_in[5];
    const float* qkv_b  = (const float*)d_in[6];
    const float* proj_w = (const float*)d_in[7];
    const float* proj_b = (const float*)d_in[8];
    const float* ln2_g  = (const float*)d_in[9];
    const float* ln2_b  = (const float*)d_in[10];
    const float* fc1_w  = (const float*)d_in[11];
    const float* fc1_b  = (const float*)d_in[12];
    const float* fc2_w  = (const float*)d_in[13];
    const float* fc2_b  = (const float*)d_in[14];
    const float* lnf_g  = (const float*)d_in[15];
    const float* lnf_b  = (const float*)d_in[16];
    float* out = (float*)d_out;

    float *h_p, *qkv_p;
    cudaGetSymbolAddress((void**)&h_p,   g_h);
    cudaGetSymbolAddress((void**)&qkv_p, g_qkv);

    __nv_bfloat16 *wq_h, *wq_l, *wp_h, *wp_l, *w1_h, *w1_l, *w2_h, *w2_l;
    __nv_bfloat16 *ah, *al, *h1h, *h1l;
    cudaGetSymbolAddress((void**)&wq_h, g_wq_h);
    cudaGetSymbolAddress((void**)&wq_l, g_wq_l);
    cudaGetSymbolAddress((void**)&wp_h, g_wp_h);
    cudaGetSymbolAddress((void**)&wp_l, g_wp_l);
    cudaGetSymbolAddress((void**)&w1_h, g_w1_h);
    cudaGetSymbolAddress((void**)&w1_l, g_w1_l);
    cudaGetSymbolAddress((void**)&w2_h, g_w2_h);
    cudaGetSymbolAddress((void**)&w2_l, g_w2_l);
    cudaGetSymbolAddress((void**)&ah,  g_ah);
    cudaGetSymbolAddress((void**)&al,  g_al);
    cudaGetSymbolAddress((void**)&h1h, g_h1h);
    cudaGetSymbolAddress((void**)&h1l, g_h1l);

    const int SMEM = 131072;
    cudaFuncSetAttribute(mma_gemm, cudaFuncAttributeMaxDynamicSharedMemorySize, SMEM);
    const int ASMEM = (QT * QK_PITCH * 3 + QT * P_PITCH) * 4;  // ~92KB
    cudaFuncSetAttribute(attn_kernel, cudaFuncAttributeMaxDynamicSharedMemorySize, ASMEM);

    wconv_kernel<<<dim3(2304/32, 768/32, DEPTH), dim3(32, 8)>>>(qkv_w, wq_h, wq_l, 768, 2304);
    wconv_kernel<<<dim3(768/32,  768/32, DEPTH), dim3(32, 8)>>>(proj_w, wp_h, wp_l, 768, 768);
    wconv_kernel<<<dim3(3072/32, 768/32, DEPTH), dim3(32, 8)>>>(fc1_w, w1_h, w1_l, 768, 3072);
    wconv_kernel<<<dim3(768/32, 3072/32, DEPTH), dim3(32, 8)>>>(fc2_w, w2_h, w2_l, 3072, 768);

    embed_kernel<<<dim3(S, B), 256>>>(x, conv_w, conv_b, h_p);

    const int ropeN = B * S * NH * (DH / 2);
    for (int l = 0; l < DEPTH; l++) {
        ln_split_kernel<<<ROWS, 256>>>(h_p, ah, al, ln1_g + l * C, ln1_b + l * C);
        mma_gemm<<<dim3(2304/128, ROWS/128), 256, SMEM>>>(
            ah, al, wq_h + (size_t)l * 2304 * 768, wq_l + (size_t)l * 2304 * 768,
            qkv_b + (size_t)l * 3 * C, nullptr, qkv_p, nullptr, nullptr, 2304, 768, 0);
        rope_kernel<<<(ropeN + 255) / 256, 256>>>(qkv_p);
        attn_kernel<<<dim3(S / QT, B * NH), ATT_THREADS, ASMEM>>>(qkv_p, ah, al);
        mma_gemm<<<dim3(768/128, ROWS/128), 256, SMEM>>>(
            ah, al, wp_h + (size_t)l * 768 * 768, wp_l + (size_t)l * 768 * 768,
            proj_b + (size_t)l * C, h_p, h_p, nullptr, nullptr, 768, 768, 0);
        ln_split_kernel<<<ROWS, 256>>>(h_p, ah, al, ln2_g + l * C, ln2_b + l * C);
        mma_gemm<<<dim3(3072/128, ROWS/128), 256, SMEM>>>(
            ah, al, w1_h + (size_t)l * 3072 * 768, w1_l + (size_t)l * 3072 * 768,
            fc1_b + (size_t)l * HID, nullptr, nullptr, h1h, h1l, 3072, 768, 1);
        mma_gemm<<<dim3(768/128, ROWS/128), 256, SMEM>>>(
            h1h, h1l, w2_h + (size_t)l * 768 * 3072, w2_l + (size_t)l * 768 * 3072,
            fc2_b + (size_t)l * C, h_p, h_p, nullptr, nullptr, 768, 3072, 0);
    }
    ln_kernel<<<ROWS, 256>>>(h_p, out, lnf_g, lnf_b);
}

// round 5
// speedup vs baseline: 3.6287x; 1.6981x over previous
#include <cuda_runtime.h>
#include <cuda_bf16.h>
#include <math.h>
#include <stdint.h>

#define B 4
#define S 800
#define C 768
#define NH 12
#define DH 64
#define HID 3072
#define DEPTH 12
#define ROWS (B*S)   // 3200

// ---------------- scratch (static device globals; no runtime alloc) ----------
__device__ float g_h  [ROWS * C];
__device__ float g_qkv[ROWS * 3 * C];

// bf16 split weights, transposed to [N,K] per layer
__device__ __nv_bfloat16 g_wq_h[DEPTH * 2304 * 768];
__device__ __nv_bfloat16 g_wq_l[DEPTH * 2304 * 768];
__device__ __nv_bfloat16 g_wp_h[DEPTH * 768 * 768];
__device__ __nv_bfloat16 g_wp_l[DEPTH * 768 * 768];
__device__ __nv_bfloat16 g_w1_h[DEPTH * 3072 * 768];
__device__ __nv_bfloat16 g_w1_l[DEPTH * 3072 * 768];
__device__ __nv_bfloat16 g_w2_h[DEPTH * 768 * 3072];
__device__ __nv_bfloat16 g_w2_l[DEPTH * 768 * 3072];
// bf16 split activations
__device__ __nv_bfloat16 g_ah [ROWS * C];
__device__ __nv_bfloat16 g_al [ROWS * C];
__device__ __nv_bfloat16 g_h1h[ROWS * HID];
__device__ __nv_bfloat16 g_h1l[ROWS * HID];
// attention operands, per-head layouts
__device__ __nv_bfloat16 g_qh [48 * 800 * 64];  // [bh][s][d]
__device__ __nv_bfloat16 g_ql [48 * 800 * 64];
__device__ __nv_bfloat16 g_kh [48 * 800 * 64];
__device__ __nv_bfloat16 g_kl [48 * 800 * 64];
__device__ __nv_bfloat16 g_vth[48 * 64 * 800];  // [bh][d][s]
__device__ __nv_bfloat16 g_vtl[48 * 64 * 800];

// ---------------- helpers ------------------------------------------------
static __device__ __forceinline__ uint32_t s2u(const void* p) {
    uint32_t a;
    asm("{ .reg .u64 t; cvta.to.shared.u64 t, %1; cvt.u32.u64 %0, t; }" : "=r"(a) : "l"(p));
    return a;
}
static __device__ __forceinline__ void ldsm4(uint32_t* r, uint32_t addr) {
    asm volatile("ldmatrix.sync.aligned.m8n8.x4.shared.b16 {%0,%1,%2,%3}, [%4];"
        : "=r"(r[0]), "=r"(r[1]), "=r"(r[2]), "=r"(r[3]) : "r"(addr));
}
static __device__ __forceinline__ void mma16816(float* c, const uint32_t* a, const uint32_t* b) {
    asm volatile("mma.sync.aligned.m16n8k16.row.col.f32.bf16.bf16.f32 "
        "{%0,%1,%2,%3}, {%4,%5,%6,%7}, {%8,%9}, {%0,%1,%2,%3};"
        : "+f"(c[0]), "+f"(c[1]), "+f"(c[2]), "+f"(c[3])
        : "r"(a[0]), "r"(a[1]), "r"(a[2]), "r"(a[3]), "r"(b[0]), "r"(b[1]));
}
#define CP_ASYNC(dst, src) \
    asm volatile("cp.async.cg.shared.global [%0], [%1], 16;" :: "r"(dst), "l"(src) : "memory")
#define CP_COMMIT() asm volatile("cp.async.commit_group;" ::: "memory")

static __device__ __forceinline__ void split_bf16(float v, __nv_bfloat16& h, __nv_bfloat16& l) {
    h = __float2bfloat16(v);
    l = __float2bfloat16(v - __bfloat162float(h));
}
static __device__ __forceinline__ uint32_t pack2(__nv_bfloat16 lo, __nv_bfloat16 hi) {
    __nv_bfloat162 t;
    t.x = lo; t.y = hi;
    return *(uint32_t*)&t;
}

// ---------------- weight split+transpose: [K,N] f32 -> [N,K] bf16 hi/lo ------
__global__ void wconv_kernel(const float* __restrict__ W, __nv_bfloat16* __restrict__ Whi,
                             __nv_bfloat16* __restrict__ Wlo, int K, int N)
{
    __shared__ float tile[32][33];
    int l = blockIdx.z;
    const float* Wl = W + (size_t)l * K * N;
    __nv_bfloat16* Oh = Whi + (size_t)l * K * N;
    __nv_bfloat16* Ol = Wlo + (size_t)l * K * N;
    int n0 = blockIdx.x * 32, k0 = blockIdx.y * 32;
    int tx = threadIdx.x, ty = threadIdx.y;
    for (int i = ty; i < 32; i += 8)
        tile[i][tx] = Wl[(size_t)(k0 + i) * N + n0 + tx];
    __syncthreads();
    for (int i = ty; i < 32; i += 8) {
        float v = tile[tx][i];
        __nv_bfloat16 h, lo;
        split_bf16(v, h, lo);
        Oh[(size_t)(n0 + i) * K + k0 + tx] = h;
        Ol[(size_t)(n0 + i) * K + k0 + tx] = lo;
    }
}

// ---------------- bf16x3 split MMA GEMM --------------------------------------
__global__ __launch_bounds__(256, 1) void mma_gemm(
    const __nv_bfloat16* __restrict__ Ah, const __nv_bfloat16* __restrict__ Al,
    const __nv_bfloat16* __restrict__ Bh, const __nv_bfloat16* __restrict__ Bl,
    const float* __restrict__ bias, const float* __restrict__ res,
    float* __restrict__ outF, __nv_bfloat16* __restrict__ outHi,
    __nv_bfloat16* __restrict__ outLo, int N, int K, int act)
{
    extern __shared__ char smem[];
    const int tid = threadIdx.x;
    const int lane = tid & 31, wid = tid >> 5;
    const int wm = wid & 1, wn = wid >> 1;
    const int m0 = blockIdx.y * 128, n0 = blockIdx.x * 128;
    const int NS = K >> 6;

    auto fill = [&](int st, int k0) {
        uint32_t sa = s2u(smem) + st * 65536;
#pragma unroll
        for (int i = 0; i < 4; i++) {
            int idx = tid + i * 256;
            int r = idx >> 3, c = idx & 7;
            int off = r * 128 + c * 16;
            int sw = off ^ ((off >> 3) & 0x70);
            size_t gA = (size_t)(m0 + r) * K + k0 + c * 8;
            size_t gB = (size_t)(n0 + r) * K + k0 + c * 8;
            CP_ASYNC(sa + sw,         Ah + gA);
            CP_ASYNC(sa + 16384 + sw, Al + gA);
            CP_ASYNC(sa + 32768 + sw, Bh + gB);
            CP_ASYNC(sa + 49152 + sw, Bl + gB);
        }
        CP_COMMIT();
    };

    float acc[4][4][4];
#pragma unroll
    for (int i = 0; i < 4; i++)
#pragma unroll
        for (int j = 0; j < 4; j++)
#pragma unroll
            for (int k = 0; k < 4; k++) acc[i][j][k] = 0.f;

    fill(0, 0);

    const int a_row = wm * 64 + (lane & 15);
    const int a_kb  = (lane >> 4) * 16;
    const int b_row = wn * 32 + (lane & 7) + ((lane >> 4) << 3);
    const int b_kb  = ((lane >> 3) & 1) * 16;

    for (int slab = 0; slab < NS; slab++) {
        if (slab + 1 < NS) {
            fill((slab + 1) & 1, (slab + 1) * 64);
            asm volatile("cp.async.wait_group 1;" ::: "memory");
        } else {
            asm volatile("cp.async.wait_group 0;" ::: "memory");
        }
        __syncthreads();
        uint32_t sa = s2u(smem) + (slab & 1) * 65536;
#pragma unroll
        for (int ks = 0; ks < 4; ks++) {
            uint32_t ahf[4][4], alf[4][4], bhf[4][2], blf[4][2];
#pragma unroll
            for (int mt = 0; mt < 4; mt++) {
                int off = (a_row + mt * 16) * 128 + ks * 32 + a_kb;
                int sw = off ^ ((off >> 3) & 0x70);
                ldsm4(ahf[mt], sa + sw);
                ldsm4(alf[mt], sa + 16384 + sw);
            }
#pragma unroll
            for (int np = 0; np < 2; np++) {
                int off = (b_row + np * 16) * 128 + ks * 32 + b_kb;
                int sw = off ^ ((off >> 3) & 0x70);
                uint32_t t[4];
                ldsm4(t, sa + 32768 + sw);
                bhf[np*2][0] = t[0]; bhf[np*2][1] = t[1];
                bhf[np*2+1][0] = t[2]; bhf[np*2+1][1] = t[3];
                ldsm4(t, sa + 49152 + sw);
                blf[np*2][0] = t[0]; blf[np*2][1] = t[1];
                blf[np*2+1][0] = t[2]; blf[np*2+1][1] = t[3];
            }
#pragma unroll
            for (int mt = 0; mt < 4; mt++)
#pragma unroll
                for (int nt = 0; nt < 4; nt++) {
                    mma16816(acc[mt][nt], ahf[mt], bhf[nt]);
                    mma16816(acc[mt][nt], ahf[mt], blf[nt]);
                    mma16816(acc[mt][nt], alf[mt], bhf[nt]);
                }
        }
        __syncthreads();
    }

    float* sOut = (float*)smem;
#pragma unroll
    for (int mt = 0; mt < 4; mt++)
#pragma unroll
        for (int nt = 0; nt < 4; nt++) {
            int m = wm * 64 + mt * 16 + (lane >> 2);
            int n = wn * 32 + nt * 8 + (lane & 3) * 2;
            *(float2*)&sOut[m * 132 + n]       = make_float2(acc[mt][nt][0], acc[mt][nt][1]);
            *(float2*)&sOut[(m + 8) * 132 + n] = make_float2(acc[mt][nt][2], acc[mt][nt][3]);
        }
    __syncthreads();

#pragma unroll
    for (int it = 0; it < 16; it++) {
        int idx = tid + it * 256;
        int row = idx >> 5, c4 = (idx & 31) * 4;
        int n = n0 + c4;
        float v[4];
#pragma unroll
        for (int j = 0; j < 4; j++) v[j] = sOut[row * 132 + c4 + j] + bias[n + j];
        size_t go = (size_t)(m0 + row) * N + n;
        if (res) {
            float4 rv = *(const float4*)(res + go);
            v[0] += rv.x; v[1] += rv.y; v[2] += rv.z; v[3] += rv.w;
        }
        if (act == 1) {
#pragma unroll
            for (int j = 0; j < 4; j++)
                v[j] = 0.5f * v[j] * (1.f + erff(v[j] * 0.70710678118654752f));
        }
        if (outF) {
            *(float4*)(outF + go) = make_float4(v[0], v[1], v[2], v[3]);
        } else {
            __nv_bfloat16 h[4], l[4];
#pragma unroll
            for (int j = 0; j < 4; j++) split_bf16(v[j], h[j], l[j]);
            *(uint2*)(outHi + go) = *(uint2*)h;
            *(uint2*)(outLo + go) = *(uint2*)l;
        }
    }
}

// ---------------- patch embed ------------------------------------------------
__global__ __launch_bounds__(256) void embed_kernel(
    const float* __restrict__ x, const float* __restrict__ w,
    const float* __restrict__ bias, float* __restrict__ out)
{
    int s = blockIdx.x, b = blockIdx.y, tid = threadIdx.x;
    __shared__ float patch[768];
    int sp    = (s < 400) ? s : s - 400;
    int choff = (s < 400) ? 0 : 3;
    int gh = sp / 20, gw = sp % 20;
    for (int j = tid; j < 768; j += 256) {
        int ci = j >> 8, ph = (j >> 4) & 15, pw = j & 15;
        patch[j] = x[(((size_t)b * 6 + choff + ci) * 320 + gh * 16 + ph) * 320 + gw * 16 + pw];
    }
    __syncthreads();
#pragma unroll
    for (int u = 0; u < 3; u++) {
        int c = tid + u * 256;
        const float4* wr = (const float4*)(w + (size_t)c * 768);
        const float4* pp = (const float4*)patch;
        float acc = bias[c];
#pragma unroll 8
        for (int j4 = 0; j4 < 192; j4++) {
            float4 wv = wr[j4], pv = pp[j4];
            acc += wv.x * pv.x + wv.y * pv.y + wv.z * pv.z + wv.w * pv.w;
        }
        out[((size_t)(b * 800 + s)) * 768 + c] = acc;
    }
}

// ---------------- layernorm (float out) --------------------------------------
__global__ __launch_bounds__(256) void ln_kernel(
    const float* __restrict__ in, float* __restrict__ out,
    const float* __restrict__ g, const float* __restrict__ bta)
{
    int row = blockIdx.x, tid = threadIdx.x;
    const float* x = in + (size_t)row * C;
    __shared__ float red[256];
    float s = 0.f;
    for (int i = tid; i < C; i += 256) s += x[i];
    red[tid] = s; __syncthreads();
    for (int st = 128; st > 0; st >>= 1) { if (tid < st) red[tid] += red[tid + st]; __syncthreads(); }
    float mean = red[0] / (float)C;
    __syncthreads();
    float v = 0.f;
    for (int i = tid; i < C; i += 256) { float d = x[i] - mean; v += d * d; }
    red[tid] = v; __syncthreads();
    for (int st = 128; st > 0; st >>= 1) { if (tid < st) red[tid] += red[tid + st]; __syncthreads(); }
    float inv = rsqrtf(red[0] / (float)C + 1e-6f);
    float* o = out + (size_t)row * C;
    for (int i = tid; i < C; i += 256) o[i] = (x[i] - mean) * inv * g[i] + bta[i];
}

// ---------------- layernorm with fused bf16 split output ---------------------
__global__ __launch_bounds__(256) void ln_split_kernel(
    const float* __restrict__ in, __nv_bfloat16* __restrict__ hi,
    __nv_bfloat16* __restrict__ lo,
    const float* __restrict__ g, const float* __restrict__ bta)
{
    int row = blockIdx.x, tid = threadIdx.x;
    const float* x = in + (size_t)row * C;
    __shared__ float red[256];
    float s = 0.f;
    for (int i = tid; i < C; i += 256) s += x[i];
    red[tid] = s; __syncthreads();
    for (int st = 128; st > 0; st >>= 1) { if (tid < st) red[tid] += red[tid + st]; __syncthreads(); }
    float mean = red[0] / (float)C;
    __syncthreads();
    float v = 0.f;
    for (int i = tid; i < C; i += 256) { float d = x[i] - mean; v += d * d; }
    red[tid] = v; __syncthreads();
    for (int st = 128; st > 0; st >>= 1) { if (tid < st) red[tid] += red[tid + st]; __syncthreads(); }
    float inv = rsqrtf(red[0] / (float)C + 1e-6f);
    for (int i = tid; i < C; i += 256) {
        float val = (x[i] - mean) * inv * g[i] + bta[i];
        __nv_bfloat16 h, l;
        split_bf16(val, h, l);
        hi[(size_t)row * C + i] = h;
        lo[(size_t)row * C + i] = l;
    }
}

// ---------------- qkv prep: rope + scale + bf16 split + V transpose ----------
// block = (stile of 80, bh). q,k: [bh][s][d]; v: transposed [bh][d][s].
__global__ __launch_bounds__(256) void qkvprep_kernel(
    const float* __restrict__ qkv,
    __nv_bfloat16* __restrict__ qh, __nv_bfloat16* __restrict__ ql,
    __nv_bfloat16* __restrict__ kh, __nv_bfloat16* __restrict__ kl,
    __nv_bfloat16* __restrict__ vth, __nv_bfloat16* __restrict__ vtl)
{
    const int st = blockIdx.x, bh = blockIdx.y;
    const int b = bh / NH, h = bh % NH;
    const int tid = threadIdx.x;
    __shared__ ushort tvh[80][66], tvl[80][66];

    // phase A: rope q,k + split. 80 s x 32 d-pairs
    for (int i = tid; i < 2560; i += 256) {
        int d2 = i & 31, sl = i >> 5;
        int s = st * 80 + sl;
        const float* base = qkv + (size_t)(b * S + s) * (3 * C) + h * DH;
        int d0 = 2 * d2, d1 = d0 + 1;
        float a0 = (float)s * powf(10000.f, -(float)(d0 & 31) / 32.f);
        float a1 = (float)s * powf(10000.f, -(float)(d1 & 31) / 32.f);
        float c0 = cosf(a0), s0 = sinf(a0);
        float c1 = cosf(a1), s1 = sinf(a1);
        float q0 = base[d0], q1 = base[d1];
        float k0 = base[C + d0], k1 = base[C + d1];
        float qr0 = (q0 * c0 - q1 * s0) * 0.125f;
        float qr1 = (q1 * c1 + q0 * s1) * 0.125f;
        float kr0 = k0 * c0 - k1 * s0;
        float kr1 = k1 * c1 + k0 * s1;
        __nv_bfloat16 h0, l0, h1, l1;
        size_t o = (size_t)bh * 51200 + (size_t)s * 64 + d0;
        split_bf16(qr0, h0, l0); split_bf16(qr1, h1, l1);
        *(uint32_t*)(qh + o) = pack2(h0, h1);
        *(uint32_t*)(ql + o) = pack2(l0, l1);
        split_bf16(kr0, h0, l0); split_bf16(kr1, h1, l1);
        *(uint32_t*)(kh + o) = pack2(h0, h1);
        *(uint32_t*)(kl + o) = pack2(l0, l1);
    }
    // phase B: v split into smem tile [s][d]
    for (int i = tid; i < 1280; i += 256) {
        int sl = i >> 4, c4 = (i & 15) * 4;
        float4 v = *(const float4*)(qkv + (size_t)(b * S + st * 80 + sl) * (3 * C) + 2 * C + h * DH + c4);
        float a[4] = {v.x, v.y, v.z, v.w};
#pragma unroll
        for (int j = 0; j < 4; j++) {
            __nv_bfloat16 hh, ll;
            split_bf16(a[j], hh, ll);
            tvh[sl][c4 + j] = *(ushort*)&hh;
            tvl[sl][c4 + j] = *(ushort*)&ll;
        }
    }
    __syncthreads();
    // write vt [d][s] (s-pairs packed in uint)
    for (int i = tid; i < 2560; i += 256) {
        int d = i / 40, sp = (i % 40) * 2;
        size_t o = (size_t)bh * 51200 + (size_t)d * 800 + st * 80 + sp;
        *(uint32_t*)(vth + o) = (uint32_t)tvh[sp][d] | ((uint32_t)tvh[sp + 1][d] << 16);
        *(uint32_t*)(vtl + o) = (uint32_t)tvl[sp][d] | ((uint32_t)tvl[sp + 1][d] << 16);
    }
}

// ---------------- tensor-core flash attention --------------------------------
// QT=80 queries/block, 5 warps (16 rows each); KT=80 keys/tile, 10 tiles.
// smem: Qh 10240 | Ql 10240 | Kh 10240 | Kl 10240 | Vh 11264 | Vl 11264
#define AQH0 0
#define AQL0 10240
#define AKH0 20480
#define AKL0 30720
#define AVH0 40960
#define AVL0 52224
#define ASMEM_SZ 63488
__global__ __launch_bounds__(160, 2) void attn_mma_kernel(
    const __nv_bfloat16* __restrict__ qh, const __nv_bfloat16* __restrict__ ql,
    const __nv_bfloat16* __restrict__ kh, const __nv_bfloat16* __restrict__ kl,
    const __nv_bfloat16* __restrict__ vth, const __nv_bfloat16* __restrict__ vtl,
    __nv_bfloat16* __restrict__ ohi, __nv_bfloat16* __restrict__ olo)
{
    extern __shared__ char smem[];
    const int qt = blockIdx.x, bh = blockIdx.y;
    const int b = bh / NH, h = bh % NH;
    const int tid = threadIdx.x, lane = tid & 31, w = tid >> 5;
    const uint32_t sb = s2u(smem);

    // load Q tile (once)
    const __nv_bfloat16* gQh = qh + (size_t)bh * 51200 + (size_t)qt * 80 * 64;
    const __nv_bfloat16* gQl = ql + (size_t)bh * 51200 + (size_t)qt * 80 * 64;
    for (int i = tid; i < 640; i += 160) {
        int r = i >> 3, cc = i & 7;
        int off = r * 128 + cc * 16, sw = off ^ ((off >> 3) & 0x70);
        *(uint4*)(smem + AQH0 + sw) = *(const uint4*)(gQh + r * 64 + cc * 8);
        *(uint4*)(smem + AQL0 + sw) = *(const uint4*)(gQl + r * 64 + cc * 8);
    }

    const int arow = w * 16 + (lane & 15);
    const int akb  = (lane >> 4) * 16;
    const int brow = (lane & 7) + ((lane >> 4) << 3);
    const int bkb  = ((lane >> 3) & 1) * 16;

    float m0 = -1e30f, m1 = -1e30f, l0 = 0.f, l1 = 0.f;
    float O[8][4] = {};

    const __nv_bfloat16* gKh = kh + (size_t)bh * 51200;
    const __nv_bfloat16* gKl = kl + (size_t)bh * 51200;
    const __nv_bfloat16* gVh = vth + (size_t)bh * 51200;
    const __nv_bfloat16* gVl = vtl + (size_t)bh * 51200;

    for (int kt = 0; kt < 10; kt++) {
        __syncthreads();
        for (int i = tid; i < 640; i += 160) {
            int r = i >> 3, cc = i & 7;
            int off = r * 128 + cc * 16, sw = off ^ ((off >> 3) & 0x70);
            size_t g = (size_t)(kt * 80 + r) * 64 + cc * 8;
            *(uint4*)(smem + AKH0 + sw) = *(const uint4*)(gKh + g);
            *(uint4*)(smem + AKL0 + sw) = *(const uint4*)(gKl + g);
        }
        for (int i = tid; i < 640; i += 160) {
            int d = i / 10, cc = i % 10;
            size_t g = (size_t)d * 800 + kt * 80 + cc * 8;
            *(uint4*)(smem + AVH0 + d * 176 + cc * 16) = *(const uint4*)(gVh + g);
            *(uint4*)(smem + AVL0 + d * 176 + cc * 16) = *(const uint4*)(gVl + g);
        }
        __syncthreads();

        // scores: 16 rows x 80 keys per warp
        float c[10][4];
#pragma unroll
        for (int nt = 0; nt < 10; nt++)
#pragma unroll
            for (int j = 0; j < 4; j++) c[nt][j] = 0.f;
#pragma unroll
        for (int ks = 0; ks < 4; ks++) {
            uint32_t ahf[4], alf[4];
            int aoff = arow * 128 + ks * 32 + akb;
            int asw = aoff ^ ((aoff >> 3) & 0x70);
            ldsm4(ahf, sb + AQH0 + asw);
            ldsm4(alf, sb + AQL0 + asw);
#pragma unroll
            for (int np = 0; np < 5; np++) {
                int boff = (np * 16 + brow) * 128 + ks * 32 + bkb;
                int bsw = boff ^ ((boff >> 3) & 0x70);
                uint32_t th[4], tl[4];
                ldsm4(th, sb + AKH0 + bsw);
                ldsm4(tl, sb + AKL0 + bsw);
                uint32_t bh0[2] = {th[0], th[1]}, bh1[2] = {th[2], th[3]};
                uint32_t bl0[2] = {tl[0], tl[1]}, bl1[2] = {tl[2], tl[3]};
                mma16816(c[2*np],   ahf, bh0); mma16816(c[2*np],   ahf, bl0); mma16816(c[2*np],   alf, bh0);
                mma16816(c[2*np+1], ahf, bh1); mma16816(c[2*np+1], ahf, bl1); mma16816(c[2*np+1], alf, bh1);
            }
        }

        // online softmax (rows r = lane>>2 and r+8)
        float mt0 = -1e30f, mt1 = -1e30f;
#pragma unroll
        for (int nt = 0; nt < 10; nt++) {
            mt0 = fmaxf(mt0, fmaxf(c[nt][0], c[nt][1]));
            mt1 = fmaxf(mt1, fmaxf(c[nt][2], c[nt][3]));
        }
        mt0 = fmaxf(mt0, __shfl_xor_sync(0xffffffffu, mt0, 1));
        mt0 = fmaxf(mt0, __shfl_xor_sync(0xffffffffu, mt0, 2));
        mt1 = fmaxf(mt1, __shfl_xor_sync(0xffffffffu, mt1, 1));
        mt1 = fmaxf(mt1, __shfl_xor_sync(0xffffffffu, mt1, 2));
        float nm0 = fmaxf(m0, mt0), nm1 = fmaxf(m1, mt1);
        float fac0 = __expf(m0 - nm0), fac1 = __expf(m1 - nm1);
        float ps0 = 0.f, ps1 = 0.f;
#pragma unroll
        for (int nt = 0; nt < 10; nt++) {
            c[nt][0] = __expf(c[nt][0] - nm0); ps0 += c[nt][0];
            c[nt][1] = __expf(c[nt][1] - nm0); ps0 += c[nt][1];
            c[nt][2] = __expf(c[nt][2] - nm1); ps1 += c[nt][2];
            c[nt][3] = __expf(c[nt][3] - nm1); ps1 += c[nt][3];
        }
        ps0 += __shfl_xor_sync(0xffffffffu, ps0, 1);
        ps0 += __shfl_xor_sync(0xffffffffu, ps0, 2);
        ps1 += __shfl_xor_sync(0xffffffffu, ps1, 1);
        ps1 += __shfl_xor_sync(0xffffffffu, ps1, 2);
        l0 = l0 * fac0 + ps0; l1 = l1 * fac1 + ps1;
        m0 = nm0; m1 = nm1;
#pragma unroll
        for (int j = 0; j < 8; j++) {
            O[j][0] *= fac0; O[j][1] *= fac0; O[j][2] *= fac1; O[j][3] *= fac1;
        }

        // PV: P (registers) @ V (smem, transposed layout)
#pragma unroll
        for (int kp = 0; kp < 5; kp++) {
            uint32_t pah[4], pal[4];
            {
                __nv_bfloat16 hh[8], ll[8];
                split_bf16(c[2*kp][0],   hh[0], ll[0]); split_bf16(c[2*kp][1],   hh[1], ll[1]);
                split_bf16(c[2*kp][2],   hh[2], ll[2]); split_bf16(c[2*kp][3],   hh[3], ll[3]);
                split_bf16(c[2*kp+1][0], hh[4], ll[4]); split_bf16(c[2*kp+1][1], hh[5], ll[5]);
                split_bf16(c[2*kp+1][2], hh[6], ll[6]); split_bf16(c[2*kp+1][3], hh[7], ll[7]);
                pah[0] = pack2(hh[0], hh[1]); pah[1] = pack2(hh[2], hh[3]);
                pah[2] = pack2(hh[4], hh[5]); pah[3] = pack2(hh[6], hh[7]);
                pal[0] = pack2(ll[0], ll[1]); pal[1] = pack2(ll[2], ll[3]);
                pal[2] = pack2(ll[4], ll[5]); pal[3] = pack2(ll[6], ll[7]);
            }
#pragma unroll
            for (int dnp = 0; dnp < 4; dnp++) {
                int voff = (dnp * 16 + brow) * 176 + kp * 32 + bkb;
                uint32_t th[4], tl[4];
                ldsm4(th, sb + AVH0 + voff);
                ldsm4(tl, sb + AVL0 + voff);
                uint32_t bh0[2] = {th[0], th[1]}, bh1[2] = {th[2], th[3]};
                uint32_t bl0[2] = {tl[0], tl[1]}, bl1[2] = {tl[2], tl[3]};
                mma16816(O[2*dnp],   pah, bh0); mma16816(O[2*dnp],   pah, bl0); mma16816(O[2*dnp],   pal, bh0);
                mma16816(O[2*dnp+1], pah, bh1); mma16816(O[2*dnp+1], pah, bl1); mma16816(O[2*dnp+1], pal, bh1);
            }
        }
    }

    // epilogue: normalize, split, store to proj-GEMM input [bs][C]
    float inv0 = 1.f / l0, inv1 = 1.f / l1;
    int row = qt * 80 + w * 16 + (lane >> 2);
    size_t g0 = (size_t)(b * S + row) * C + h * DH + (lane & 3) * 2;
    size_t g1 = g0 + 8 * C;
#pragma unroll
    for (int nt = 0; nt < 8; nt++) {
        __nv_bfloat16 hh, ll, hh2, ll2;
        float v0 = O[nt][0] * inv0, v1 = O[nt][1] * inv0;
        split_bf16(v0, hh, ll); split_bf16(v1, hh2, ll2);
        *(uint32_t*)(ohi + g0 + nt * 8) = pack2(hh, hh2);
        *(uint32_t*)(olo + g0 + nt * 8) = pack2(ll, ll2);
        float v2 = O[nt][2] * inv1, v3 = O[nt][3] * inv1;
        split_bf16(v2, hh, ll); split_bf16(v3, hh2, ll2);
        *(uint32_t*)(ohi + g1 + nt * 8) = pack2(hh, hh2);
        *(uint32_t*)(olo + g1 + nt * 8) = pack2(ll, ll2);
    }
}

// ---------------- host orchestration ----------------------------------------
extern "C" void kernel_launch(void* const* d_in, const int* in_sizes, int n_in,
                              void* d_out, int out_size)
{
    const float* x      = (const float*)d_in[0];
    const float* conv_w = (const float*)d_in[1];
    const float* conv_b = (const float*)d_in[2];
    const float* ln1_g  = (const float*)d_in[3];
    const float* ln1_b  = (const float*)d_in[4];
    const float* qkv_w  = (const float*)d_in[5];
    const float* qkv_b  = (const float*)d_in[6];
    const float* proj_w = (const float*)d_in[7];
    const float* proj_b = (const float*)d_in[8];
    const float* ln2_g  = (const float*)d_in[9];
    const float* ln2_b  = (const float*)d_in[10];
    const float* fc1_w  = (const float*)d_in[11];
    const float* fc1_b  = (const float*)d_in[12];
    const float* fc2_w  = (const float*)d_in[13];
    const float* fc2_b  = (const float*)d_in[14];
    const float* lnf_g  = (const float*)d_in[15];
    const float* lnf_b  = (const float*)d_in[16];
    float* out = (float*)d_out;

    float *h_p, *qkv_p;
    cudaGetSymbolAddress((void**)&h_p,   g_h);
    cudaGetSymbolAddress((void**)&qkv_p, g_qkv);

    __nv_bfloat16 *wq_h, *wq_l, *wp_h, *wp_l, *w1_h, *w1_l, *w2_h, *w2_l;
    __nv_bfloat16 *ah, *al, *h1h, *h1l;
    __nv_bfloat16 *qhp, *qlp, *khp, *klp, *vthp, *vtlp;
    cudaGetSymbolAddress((void**)&wq_h, g_wq_h);
    cudaGetSymbolAddress((void**)&wq_l, g_wq_l);
    cudaGetSymbolAddress((void**)&wp_h, g_wp_h);
    cudaGetSymbolAddress((void**)&wp_l, g_wp_l);
    cudaGetSymbolAddress((void**)&w1_h, g_w1_h);
    cudaGetSymbolAddress((void**)&w1_l, g_w1_l);
    cudaGetSymbolAddress((void**)&w2_h, g_w2_h);
    cudaGetSymbolAddress((void**)&w2_l, g_w2_l);
    cudaGetSymbolAddress((void**)&ah,  g_ah);
    cudaGetSymbolAddress((void**)&al,  g_al);
    cudaGetSymbolAddress((void**)&h1h, g_h1h);
    cudaGetSymbolAddress((void**)&h1l, g_h1l);
    cudaGetSymbolAddress((void**)&qhp,  g_qh);
    cudaGetSymbolAddress((void**)&qlp,  g_ql);
    cudaGetSymbolAddress((void**)&khp,  g_kh);
    cudaGetSymbolAddress((void**)&klp,  g_kl);
    cudaGetSymbolAddress((void**)&vthp, g_vth);
    cudaGetSymbolAddress((void**)&vtlp, g_vtl);

    const int SMEM = 131072;
    cudaFuncSetAttribute(mma_gemm, cudaFuncAttributeMaxDynamicSharedMemorySize, SMEM);
    cudaFuncSetAttribute(attn_mma_kernel, cudaFuncAttributeMaxDynamicSharedMemorySize, ASMEM_SZ);

    wconv_kernel<<<dim3(2304/32, 768/32, DEPTH), dim3(32, 8)>>>(qkv_w, wq_h, wq_l, 768, 2304);
    wconv_kernel<<<dim3(768/32,  768/32, DEPTH), dim3(32, 8)>>>(proj_w, wp_h, wp_l, 768, 768);
    wconv_kernel<<<dim3(3072/32, 768/32, DEPTH), dim3(32, 8)>>>(fc1_w, w1_h, w1_l, 768, 3072);
    wconv_kernel<<<dim3(768/32, 3072/32, DEPTH), dim3(32, 8)>>>(fc2_w, w2_h, w2_l, 3072, 768);

    embed_kernel<<<dim3(S, B), 256>>>(x, conv_w, conv_b, h_p);

    for (int l = 0; l < DEPTH; l++) {
        ln_split_kernel<<<ROWS, 256>>>(h_p, ah, al, ln1_g + l * C, ln1_b + l * C);
        mma_gemm<<<dim3(2304/128, ROWS/128), 256, SMEM>>>(
            ah, al, wq_h + (size_t)l * 2304 * 768, wq_l + (size_t)l * 2304 * 768,
            qkv_b + (size_t)l * 3 * C, nullptr, qkv_p, nullptr, nullptr, 2304, 768, 0);
        qkvprep_kernel<<<dim3(10, 48), 256>>>(qkv_p, qhp, qlp, khp, klp, vthp, vtlp);
        attn_mma_kernel<<<dim3(10, 48), 160, ASMEM_SZ>>>(qhp, qlp, khp, klp, vthp, vtlp, ah, al);
        mma_gemm<<<dim3(768/128, ROWS/128), 256, SMEM>>>(
            ah, al, wp_h + (size_t)l * 768 * 768, wp_l + (size_t)l * 768 * 768,
            proj_b + (size_t)l * C, h_p, h_p, nullptr, nullptr, 768, 768, 0);
        ln_split_kernel<<<ROWS, 256>>>(h_p, ah, al, ln2_g + l * C, ln2_b + l * C);
        mma_gemm<<<dim3(3072/128, ROWS/128), 256, SMEM>>>(
            ah, al, w1_h + (size_t)l * 3072 * 768, w1_l + (size_t)l * 3072 * 768,
            fc1_b + (size_t)l * HID, nullptr, nullptr, h1h, h1l, 3072, 768, 1);
        mma_gemm<<<dim3(768/128, ROWS/128), 256, SMEM>>>(
            h1h, h1l, w2_h + (size_t)l * 768 * 3072, w2_l + (size_t)l * 768 * 3072,
            fc2_b + (size_t)l * C, h_p, h_p, nullptr, nullptr, 768, 3072, 0);
    }
    ln_kernel<<<ROWS, 256>>>(h_p, out, lnf_g, lnf_b);
}